// round 15
// baseline (speedup 1.0000x reference)
#include <cuda_runtime.h>

#define HW      65536
#define NF4     16384        // float4 per image
#define HALF4   8192         // float4 per half
#define BATCH   64
#define NTB     128
#define NBLK    256
#define NK      100
#define SHIFT   19
#define NB2     8192
#define SCAP    2048
#define KEEP    512
#define KS1     24           // target on 4096 samples -> ~384 survivors/half
#define TPB     512
#define NW      (TPB / 32)
#define FULLM   0xffffffffu
#define D2R     0.017453292519943295f

__device__ unsigned long long g_seg[NTB][2][SCAP];
__device__ unsigned g_hcnt[NTB][2];
__device__ unsigned g_hthr[NTB][2];
__device__ unsigned g_rdv[NTB];
__device__ float    g_xy[2][BATCH][NK][2];
__device__ float    g_pre[BATCH][NK][8];
__device__ float    g_part[BATCH][2];
__device__ unsigned g_pair[BATCH];
__device__ unsigned g_done = 0;

__device__ __forceinline__ unsigned fkey(float f) {
    unsigned u = __float_as_uint(f);
    return u ^ ((unsigned)((int)u >> 31) | 0x80000000u);
}
__device__ __forceinline__ float inv_fkey(unsigned k) {
    unsigned u = (k & 0x80000000u) ? (k ^ 0x80000000u) : ~k;
    return __uint_as_float(u);
}

__device__ void suffix_find(const unsigned* hist, int NB, unsigned K,
                            unsigned* s_ws, unsigned* s_bin, unsigned* s_above) {
    int tid  = threadIdx.x;
    int lane = tid & 31, warp = tid >> 5;
    int bpt  = (NB + TPB - 1) / TPB;
    int base = tid * bpt;
    unsigned p = 0;
    for (int j = 0; j < bpt; j++) {
        int b = base + j;
        if (b < NB) p += hist[b];
    }
    unsigned v = p;
    for (int d = 1; d < 32; d <<= 1) {
        unsigned o = __shfl_down_sync(FULLM, v, d);
        if (lane + d < 32) v += o;
    }
    if (lane == 0) s_ws[warp] = v;
    __syncthreads();
    unsigned add = 0;
    for (int w = warp + 1; w < NW; w++) add += s_ws[w];
    unsigned sAfter = (v - p) + add;
    if (sAfter < K && sAfter + p >= K) {
        unsigned cum = sAfter;
        for (int j = bpt - 1; j >= 0; j--) {
            int b = base + j;
            if (b >= NB) continue;
            unsigned h = hist[b];
            if (cum + h >= K) { *s_bin = (unsigned)b; *s_above = cum; break; }
            cum += h;
        }
    }
    __syncthreads();
}

__device__ __forceinline__ float gwd_one(float xp, float yp, float wp, float hp, float ap,
                                         float xt, float yt, float wt, float ht, float at) {
    wp = fminf(fmaxf(wp, 1e-7f), 1e7f);
    hp = fminf(fmaxf(hp, 1e-7f), 1e7f);
    wt = fminf(fmaxf(wt, 1e-7f), 1e7f);
    ht = fminf(fmaxf(ht, 1e-7f), 1e7f);
    float sp, cp, st, ct;
    sincosf(ap * D2R, &sp, &cp);
    sincosf(at * D2R, &st, &ct);
    float s1p = 0.5f * wp, s2p = 0.5f * hp, s1t = 0.5f * wt, s2t = 0.5f * ht;
    float dx = xp - xt, dy = yp - yt;
    float xyd = dx * dx + dy * dy;
    float q1p = s1p * s1p, q2p = s2p * s2p, q1t = s1t * s1t, q2t = s2t * s2t;
    float Ap = cp * cp * q1p + sp * sp * q2p;
    float Bp = cp * sp * (q1p - q2p);
    float Cp = sp * sp * q1p + cp * cp * q2p;
    float At = ct * ct * q1t + st * st * q2t;
    float Bt = ct * st * (q1t - q2t);
    float Ct = st * st * q1t + ct * ct * q2t;
    float whr  = q1p + q2p + q1t + q2t;
    float tr   = Ap * At + 2.f * Bp * Bt + Cp * Ct;
    float dets = s1p * s2p * s1t * s2t;
    whr -= 2.f * sqrtf(fmaxf(tr + 2.f * dets, 0.f));
    float d = fmaxf(xyd + whr, 0.f);
    d = log1pf(d);
    return 1.f - 1.f / (1.f + d);
}

// smem- or gmem-destination push with shared counter
__device__ __forceinline__ void push4(float4 f, int gidx4, float thresh,
                                      unsigned long long* dst, unsigned* s_cnt,
                                      unsigned cap) {
    float mx = fmaxf(fmaxf(f.x, f.y), fmaxf(f.z, f.w));
    if (mx < thresh) return;
    float v[4] = {f.x, f.y, f.z, f.w};
#pragma unroll
    for (int c = 0; c < 4; c++) {
        if (v[c] >= thresh) {
            unsigned pos = atomicAdd(s_cnt, 1u);
            if (pos < cap) {
                unsigned idx = (unsigned)(gidx4 * 4 + c);
                dst[pos] = ((unsigned long long)fkey(v[c]) << 16) |
                           (unsigned long long)(65535u - idx);
            }
        }
    }
}

__global__ void __launch_bounds__(TPB)
fused_all(const float* __restrict__ hm_p, const float* __restrict__ hm_t,
          const float* __restrict__ ab_p, const float* __restrict__ ang_p,
          const float* __restrict__ ab_t, const float* __restrict__ ang_t,
          const int* __restrict__ ind, const int* __restrict__ msk,
          float* __restrict__ out) {
    __shared__ __align__(16) unsigned sh_hist[NB2];   // 32KB: exact hist OR cand
    unsigned long long* cand = (unsigned long long*)sh_hist;   // 4096 ull
    __shared__ __align__(16) unsigned long long keep[KEEP];    // 4KB
    __shared__ unsigned rh[256];
    __shared__ unsigned s_ws[NW];
    __shared__ unsigned s_bin, s_above, s_cnt, s_kcnt, s_mrg, s_sec, s_last;
    __shared__ float rl[NW], rm[NW];

    int tid  = threadIdx.x;
    int lane = tid & 31, warp = tid >> 5;
    int bid  = blockIdx.x;
    int tb   = bid >> 1;
    int half = bid & 1;
    int tensor = (tb >= BATCH) ? 1 : 0;
    int batch  = tb & 63;
    const float4* src4 = (const float4*)
        (tensor ? hm_t + (size_t)batch * HW : hm_p + (size_t)batch * HW);
    const float4* srch = src4 + half * HALF4;

    // ---- Stage loss inputs (one block per batch) ----
    if (tensor == 0 && half == 0 && tid < NK) {
        int r   = batch * NK + tid;
        float m = (float)msk[r];
        int id  = ind[r];
        size_t ab_base = (size_t)batch * (2 * HW);
        g_pre[batch][tid][0] = ab_p[ab_base + id] * 2.f * m;
        g_pre[batch][tid][1] = ab_p[ab_base + HW + id] * 2.f * m;
        g_pre[batch][tid][2] = (ang_p[(size_t)batch * HW + id] - 90.f) * m;
        g_pre[batch][tid][3] = ab_t[r * 2] * 2.f * m;
        g_pre[batch][tid][4] = ab_t[r * 2 + 1] * 2.f * m;
        g_pre[batch][tid][5] = (ang_t[r] - 90.f) * m;
        g_pre[batch][tid][6] = m;
    }

    // ---- Phase 1: 4096 own-half samples -> 16-bit threshold ----
    unsigned keys[8];
#pragma unroll
    for (int c = 0; c < 2; c++) {
        float4 f = srch[c * (HALF4 / 2) + tid];
        keys[4 * c + 0] = fkey(f.x);
        keys[4 * c + 1] = fkey(f.y);
        keys[4 * c + 2] = fkey(f.z);
        keys[4 * c + 3] = fkey(f.w);
    }
    if (tid < 256) rh[tid] = 0;
    __syncthreads();
#pragma unroll
    for (int i = 0; i < 8; i++) atomicAdd(&rh[keys[i] >> 24], 1u);
    __syncthreads();
    suffix_find(rh, 256, KS1, s_ws, &s_bin, &s_above);
    unsigned c0 = s_bin, a0 = s_above;
    __syncthreads();
    if (tid < 256) rh[tid] = 0;
    __syncthreads();
#pragma unroll
    for (int i = 0; i < 8; i++)
        if ((keys[i] >> 24) == c0) atomicAdd(&rh[(keys[i] >> 16) & 255u], 1u);
    __syncthreads();
    suffix_find(rh, 256, KS1 - a0, s_ws, &s_bin, &s_above);
    unsigned thrkey = (c0 << 24) | (s_bin << 16);
    float thresh = inv_fkey(thrkey);

    // ---- Phase 2: collect own half into global segment ----
    if (tid == 0) s_cnt = 0;
    __syncthreads();
    unsigned long long* seg = g_seg[tb][half];
#pragma unroll
    for (int b = 0; b < 2; b++) {
        float4 fa[8];
#pragma unroll
        for (int u = 0; u < 8; u++)
            fa[u] = __ldcs(&srch[tid + (8 * b + u) * TPB]);
#pragma unroll
        for (int u = 0; u < 8; u++)
            push4(fa[u], half * HALF4 + tid + (8 * b + u) * TPB,
                  thresh, seg, &s_cnt, SCAP);
    }
    __syncthreads();
    if (tid == 0) {
        g_hcnt[tb][half] = s_cnt;
        g_hthr[tb][half] = thrkey;
        __threadfence();
        s_mrg = (atomicAdd(&g_rdv[tb], 1u) == 1u);   // second arriver merges
    }
    __syncthreads();
    if (!s_mrg) return;   // first arriver exits; no waiting, no deadlock
    __threadfence();      // acquire peer half's seg/cnt/thr

    // ---- Merge + refine (merger block only) ----
    unsigned cnt0 = g_hcnt[tb][0], cnt1 = g_hcnt[tb][1];
    unsigned thr0 = g_hthr[tb][0], thr1 = g_hthr[tb][1];
    unsigned thrbase = thr0 < thr1 ? thr0 : thr1;
    unsigned rshift = 9;
    bool need_exact = (cnt0 < NK) || (cnt1 < NK) || (cnt0 > SCAP) || (cnt1 > SCAP);
    unsigned kc = 0;

    if (!need_exact) {
        if (tid < 256) rh[tid] = 0;
        if (tid == 0) s_kcnt = 0;
        __syncthreads();
#pragma unroll
        for (int h = 0; h < 2; h++) {
            const unsigned long long* sg = g_seg[tb][h];
            unsigned c = h ? cnt1 : cnt0;
            for (unsigned i = tid; i < c; i += TPB) {
                unsigned key = (unsigned)(sg[i] >> 16);
                unsigned off = (key - thrbase) >> rshift;
                if (off > 255u) off = 255u;
                atomicAdd(&rh[off], 1u);
            }
        }
        __syncthreads();
        suffix_find(rh, 256, NK, s_ws, &s_bin, &s_above);
        unsigned r0 = s_bin;
#pragma unroll
        for (int h = 0; h < 2; h++) {
            const unsigned long long* sg = g_seg[tb][h];
            unsigned c = h ? cnt1 : cnt0;
            for (unsigned i = tid; i < c; i += TPB) {
                unsigned long long e = sg[i];
                unsigned key = (unsigned)(e >> 16);
                unsigned off = (key - thrbase) >> rshift;
                if (off > 255u) off = 255u;
                if (off >= r0) {
                    unsigned p = atomicAdd(&s_kcnt, 1u);
                    if (p < KEEP) keep[p] = e;
                }
            }
        }
        __syncthreads();
        kc = s_kcnt;
        if (kc > KEEP) need_exact = true;
        __syncthreads();
    }

    unsigned long long* buf = keep;
    unsigned n = kc;

    if (need_exact) {
        // full exact path over the whole image (proven fallback)
        for (int i = tid; i < NB2; i += TPB) sh_hist[i] = 0;
        __syncthreads();
        for (int j = 0; j < NF4 / TPB; j++) {
            float4 f = src4[tid + j * TPB];
            atomicAdd(&sh_hist[fkey(f.x) >> SHIFT], 1u);
            atomicAdd(&sh_hist[fkey(f.y) >> SHIFT], 1u);
            atomicAdd(&sh_hist[fkey(f.z) >> SHIFT], 1u);
            atomicAdd(&sh_hist[fkey(f.w) >> SHIFT], 1u);
        }
        __syncthreads();
        suffix_find(sh_hist, NB2, NK, s_ws, &s_bin, &s_above);
        thrbase = s_bin << SHIFT;
        float th = inv_fkey(thrbase);
        rshift = SHIFT - 8;
        if (tid == 0) s_cnt = 0;
        __syncthreads();
        for (int j = 0; j < NF4 / TPB; j++) {
            float4 f = src4[tid + j * TPB];
            push4(f, tid + j * TPB, th, cand, &s_cnt, 4096);
        }
        __syncthreads();
        unsigned Mc = s_cnt;
        if (Mc > 4096) Mc = 4096;
        if (tid < 256) rh[tid] = 0;
        if (tid == 0) s_kcnt = 0;
        __syncthreads();
        for (unsigned i = tid; i < Mc; i += TPB) {
            unsigned key = (unsigned)(cand[i] >> 16);
            unsigned off = (key - thrbase) >> rshift;
            if (off > 255u) off = 255u;
            atomicAdd(&rh[off], 1u);
        }
        __syncthreads();
        suffix_find(rh, 256, NK, s_ws, &s_bin, &s_above);
        unsigned r0 = s_bin;
        for (unsigned i = tid; i < Mc; i += TPB) {
            unsigned long long e = cand[i];
            unsigned key = (unsigned)(e >> 16);
            unsigned off = (key - thrbase) >> rshift;
            if (off > 255u) off = 255u;
            if (off >= r0) {
                unsigned p = atomicAdd(&s_kcnt, 1u);
                if (p < KEEP) keep[p] = e;
            }
        }
        __syncthreads();
        kc = s_kcnt;
        if (kc > KEEP) { buf = cand; n = Mc; }   // tie storm: sort everything
        else           { buf = keep; n = kc; }
    }

    // ---- Sort desc on (key, 65535-idx) => jax tie order ----
    unsigned P2 = 128;
    while (P2 < n) P2 <<= 1;
    for (unsigned i = n + tid; i < P2; i += TPB) buf[i] = 0ULL;
    __syncthreads();
    if (P2 <= TPB) {
        unsigned long long v = (tid < (int)P2) ? buf[tid] : 0ULL;
        for (unsigned k = 2; k <= P2; k <<= 1) {
            for (unsigned j = k >> 1; j > 0; j >>= 1) {
                unsigned long long o;
                if (j >= 32) {
                    if (tid < (int)P2) buf[tid] = v;
                    __syncthreads();
                    o = (tid < (int)P2) ? buf[tid ^ j] : 0ULL;
                    __syncthreads();
                } else {
                    o = __shfl_xor_sync(FULLM, v, j);
                }
                if (tid < (int)P2) {
                    bool kmax = (((unsigned)tid & j) == 0) == (((unsigned)tid & k) == 0);
                    v = kmax ? (v > o ? v : o) : (v < o ? v : o);
                }
            }
        }
        if (tid < (int)P2) buf[tid] = v;
        __syncthreads();
    } else {
        for (unsigned k = 2; k <= P2; k <<= 1) {
            for (unsigned j = k >> 1; j > 0; j >>= 1) {
                for (unsigned i = tid; i < P2; i += TPB) {
                    unsigned ixj = i ^ j;
                    if (ixj > i) {
                        unsigned long long a = buf[i], b = buf[ixj];
                        bool up = (i & k) == 0;
                        if (up ? (a < b) : (a > b)) { buf[i] = b; buf[ixj] = a; }
                    }
                }
                __syncthreads();
            }
        }
    }

    if (tid < NK) {
        unsigned idx = 65535u - (unsigned)(buf[tid] & 0xFFFFULL);
        g_xy[tensor][batch][tid][0] = (float)(idx & 255u);
        g_xy[tensor][batch][tid][1] = (float)(idx >> 8);
    }
    __syncthreads();

    // ---- Batch rendezvous: second merger of this batch computes the loss ----
    if (tid == 0) {
        __threadfence();
        s_sec = (atomicAdd(&g_pair[batch], 1u) == 1u);
    }
    __syncthreads();
    if (s_sec) {
        __threadfence();
        float loss = 0.f, mval = 0.f;
        if (tid < NK) {
            const float* pre = g_pre[batch][tid];
            float m  = pre[6];
            float xp = g_xy[0][batch][tid][0] * m, yp = g_xy[0][batch][tid][1] * m;
            float xt = g_xy[1][batch][tid][0] * m, yt = g_xy[1][batch][tid][1] * m;
            loss = gwd_one(xp, yp, pre[0], pre[1], pre[2],
                           xt, yt, pre[3], pre[4], pre[5]);
            mval = m;
        }
        for (int d = 16; d > 0; d >>= 1) {
            loss += __shfl_down_sync(FULLM, loss, d);
            mval += __shfl_down_sync(FULLM, mval, d);
        }
        if (lane == 0) { rl[warp] = loss; rm[warp] = mval; }
        __syncthreads();
        if (tid == 0) {
            float l = 0.f, m = 0.f;
            for (int w = 0; w < 4; w++) { l += rl[w]; m += rm[w]; }
            g_part[batch][0] = l;
            g_part[batch][1] = m;
        }
        __syncthreads();
    }

    // ---- Last of 128 mergers writes the final scalar + resets counters ----
    if (tid == 0) {
        __threadfence();
        s_last = (atomicAdd(&g_done, 1u) == (unsigned)(NTB - 1));
    }
    __syncthreads();
    if (!s_last) return;
    __threadfence();
    if (tid < BATCH) {
        float l = g_part[tid][0], m = g_part[tid][1];
        for (int d = 16; d > 0; d >>= 1) {
            l += __shfl_down_sync(FULLM, l, d);
            m += __shfl_down_sync(FULLM, m, d);
        }
        if (lane == 0) { rl[tid >> 5] = l; rm[tid >> 5] = m; }
    }
    __syncthreads();
    if (tid == 0) {
        out[0] = (rl[0] + rl[1]) / ((rm[0] + rm[1]) + 1e-8f);
        g_done = 0;
    }
    for (int i = tid; i < NTB; i += TPB) g_rdv[i] = 0;
    for (int i = tid; i < BATCH; i += TPB) g_pair[i] = 0;
}

extern "C" void kernel_launch(void* const* d_in, const int* in_sizes, int n_in,
                              void* d_out, int out_size) {
    const float* hm_p  = (const float*)d_in[0];
    const float* ab_p  = (const float*)d_in[1];
    const float* ang_p = (const float*)d_in[2];
    const float* hm_t  = (const float*)d_in[3];
    const float* ab_t  = (const float*)d_in[4];
    const float* ang_t = (const float*)d_in[5];
    const int*   ind   = (const int*)d_in[6];
    const int*   msk   = (const int*)d_in[7];
    float*       out   = (float*)d_out;

    fused_all<<<NBLK, TPB>>>(hm_p, hm_t, ab_p, ang_p, ab_t, ang_t, ind, msk, out);
}

// round 16
// speedup vs baseline: 1.1699x; 1.1699x over previous
#include <cuda_runtime.h>

#define HW      65536
#define NF4     16384        // HW/4
#define BATCH   64
#define NTB     128
#define NK      100
#define SHIFT   19
#define NB2     8192
#define CAP2    2048
#define KEEP    512
#define KS1     48           // sample target on 8192 samples (~384 expected survivors)
#define TPB     1024
#define NW      (TPB / 32)
#define FULLM   0xffffffffu
#define D2R     0.017453292519943295f

__device__ float    g_xy[2][BATCH][NK][2];
__device__ float    g_pre[BATCH][NK][8];   // wp,hp,ap,wt,ht,at,m,pad
__device__ float    g_part[BATCH][2];
__device__ unsigned g_pair[BATCH];
__device__ unsigned g_done = 0;

__device__ __forceinline__ unsigned fkey(float f) {
    unsigned u = __float_as_uint(f);
    return u ^ ((unsigned)((int)u >> 31) | 0x80000000u);
}
__device__ __forceinline__ float inv_fkey(unsigned k) {
    unsigned u = (k & 0x80000000u) ? (k ^ 0x80000000u) : ~k;
    return __uint_as_float(u);
}

// Find bin b with (count in bins > b) < K <= (count in bins >= b). Block-collective.
__device__ void suffix_find(const unsigned* hist, int NB, unsigned K,
                            unsigned* s_ws, unsigned* s_bin, unsigned* s_above) {
    int tid  = threadIdx.x;
    int lane = tid & 31, warp = tid >> 5;
    int bpt  = (NB + TPB - 1) / TPB;
    int base = tid * bpt;
    unsigned p = 0;
    for (int j = 0; j < bpt; j++) {
        int b = base + j;
        if (b < NB) p += hist[b];
    }
    unsigned v = p;
    for (int d = 1; d < 32; d <<= 1) {
        unsigned o = __shfl_down_sync(FULLM, v, d);
        if (lane + d < 32) v += o;
    }
    if (lane == 0) s_ws[warp] = v;
    __syncthreads();
    unsigned add = 0;
    for (int w = warp + 1; w < NW; w++) add += s_ws[w];
    unsigned sAfter = (v - p) + add;
    if (sAfter < K && sAfter + p >= K) {
        unsigned cum = sAfter;
        for (int j = bpt - 1; j >= 0; j--) {
            int b = base + j;
            if (b >= NB) continue;
            unsigned h = hist[b];
            if (cum + h >= K) { *s_bin = (unsigned)b; *s_above = cum; break; }
            cum += h;
        }
    }
    __syncthreads();
}

__device__ __forceinline__ float gwd_one(float xp, float yp, float wp, float hp, float ap,
                                         float xt, float yt, float wt, float ht, float at) {
    wp = fminf(fmaxf(wp, 1e-7f), 1e7f);
    hp = fminf(fmaxf(hp, 1e-7f), 1e7f);
    wt = fminf(fmaxf(wt, 1e-7f), 1e7f);
    ht = fminf(fmaxf(ht, 1e-7f), 1e7f);
    float sp, cp, st, ct;
    sincosf(ap * D2R, &sp, &cp);
    sincosf(at * D2R, &st, &ct);
    float s1p = 0.5f * wp, s2p = 0.5f * hp, s1t = 0.5f * wt, s2t = 0.5f * ht;
    float dx = xp - xt, dy = yp - yt;
    float xyd = dx * dx + dy * dy;
    float q1p = s1p * s1p, q2p = s2p * s2p, q1t = s1t * s1t, q2t = s2t * s2t;
    float Ap = cp * cp * q1p + sp * sp * q2p;
    float Bp = cp * sp * (q1p - q2p);
    float Cp = sp * sp * q1p + cp * cp * q2p;
    float At = ct * ct * q1t + st * st * q2t;
    float Bt = ct * st * (q1t - q2t);
    float Ct = st * st * q1t + ct * ct * q2t;
    float whr  = q1p + q2p + q1t + q2t;
    float tr   = Ap * At + 2.f * Bp * Bt + Cp * Ct;
    float dets = s1p * s2p * s1t * s2t;
    whr -= 2.f * sqrtf(fmaxf(tr + 2.f * dets, 0.f));
    float d = fmaxf(xyd + whr, 0.f);
    d = log1pf(d);
    return 1.f - 1.f / (1.f + d);
}

__device__ __forceinline__ void push4(float4 f, int gidx4, float thresh,
                                      unsigned long long* cand, unsigned* s_cnt,
                                      unsigned cap) {
    // fast reject: 97%+ of quads have no survivor
    float mx = fmaxf(fmaxf(f.x, f.y), fmaxf(f.z, f.w));
    if (mx < thresh) return;
    float v[4] = {f.x, f.y, f.z, f.w};
#pragma unroll
    for (int c = 0; c < 4; c++) {
        if (v[c] >= thresh) {
            unsigned pos = atomicAdd(s_cnt, 1u);
            if (pos < cap) {
                unsigned idx = (unsigned)(gidx4 * 4 + c);
                cand[pos] = ((unsigned long long)fkey(v[c]) << 16) |
                            (unsigned long long)(65535u - idx);
            }
        }
    }
}

__global__ void __launch_bounds__(TPB)
fused_all(const float* __restrict__ hm_p, const float* __restrict__ hm_t,
          const float* __restrict__ ab_p, const float* __restrict__ ang_p,
          const float* __restrict__ ab_t, const float* __restrict__ ang_t,
          const int* __restrict__ ind, const int* __restrict__ msk,
          float* __restrict__ out) {
    __shared__ __align__(16) unsigned sh_hist[NB2];   // 32KB union region
    unsigned long long* cand = (unsigned long long*)sh_hist;             // [0,16K)
    unsigned long long* keep = (unsigned long long*)(sh_hist + 4096);    // [16K,20K)
    __shared__ unsigned rh[256];
    __shared__ unsigned s_ws[NW];
    __shared__ unsigned s_bin, s_above, s_cnt, s_kcnt, s_sec, s_last;
    __shared__ float rl[NW], rm[NW];

    int tid  = threadIdx.x;
    int lane = tid & 31, warp = tid >> 5;
    unsigned lmask = (1u << lane) - 1u;
    (void)lmask;
    int tb     = blockIdx.x;              // 0..63 = hm_p, 64..127 = hm_t
    int tensor = (tb >= BATCH) ? 1 : 0;
    int batch  = tb & 63;
    const float4* src4 = (const float4*)
        (tensor ? hm_t + (size_t)batch * HW : hm_p + (size_t)batch * HW);

    // ---- Stage loss inputs (blocks 0..63, tid<NK; overlaps sample) ----
    if (tensor == 0 && tid < NK) {
        int r   = batch * NK + tid;
        float m = (float)msk[r];
        int id  = ind[r];
        size_t ab_base = (size_t)batch * (2 * HW);
        g_pre[batch][tid][0] = ab_p[ab_base + id] * 2.f * m;
        g_pre[batch][tid][1] = ab_p[ab_base + HW + id] * 2.f * m;
        g_pre[batch][tid][2] = (ang_p[(size_t)batch * HW + id] - 90.f) * m;
        g_pre[batch][tid][3] = ab_t[r * 2] * 2.f * m;
        g_pre[batch][tid][4] = ab_t[r * 2 + 1] * 2.f * m;
        g_pre[batch][tid][5] = (ang_t[r] - 90.f) * m;
        g_pre[batch][tid][6] = m;
    }

    // ---- Phase 1: 8192 coalesced samples -> 16-bit key threshold ----
    unsigned keys[8];
#pragma unroll
    for (int c = 0; c < 2; c++) {
        float4 f = src4[c * (NF4 / 2) + tid];
        keys[4 * c + 0] = fkey(f.x);
        keys[4 * c + 1] = fkey(f.y);
        keys[4 * c + 2] = fkey(f.z);
        keys[4 * c + 3] = fkey(f.w);
    }
    if (tid < 256) rh[tid] = 0;
    __syncthreads();
#pragma unroll
    for (int i = 0; i < 8; i++) atomicAdd(&rh[keys[i] >> 24], 1u);
    __syncthreads();
    suffix_find(rh, 256, KS1, s_ws, &s_bin, &s_above);
    unsigned c0 = s_bin, a0 = s_above;
    __syncthreads();
    if (tid < 256) rh[tid] = 0;
    __syncthreads();
#pragma unroll
    for (int i = 0; i < 8; i++)
        if ((keys[i] >> 24) == c0) atomicAdd(&rh[(keys[i] >> 16) & 255u], 1u);
    __syncthreads();
    suffix_find(rh, 256, KS1 - a0, s_ws, &s_bin, &s_above);
    unsigned thrkey = (c0 << 24) | (s_bin << 16);
    float thresh = inv_fkey(thrkey);

    // ---- Phase 2: one full streaming pass, 8-deep batched loads ----
    if (tid == 0) s_cnt = 0;
    __syncthreads();
#pragma unroll
    for (int b = 0; b < 2; b++) {
        float4 fa[8];
#pragma unroll
        for (int u = 0; u < 8; u++)
            fa[u] = __ldcs(&src4[tid + (8 * b + u) * TPB]);
#pragma unroll
        for (int u = 0; u < 8; u++)
            push4(fa[u], tid + (8 * b + u) * TPB, thresh, cand, &s_cnt, CAP2);
    }
    __syncthreads();
    unsigned Mc = s_cnt;
    unsigned rshift = 9;
    unsigned thrbase = thrkey;
    bool need_exact = (Mc < NK) || (Mc > CAP2);

    if (need_exact) {
        // exact 13-bit histogram + recollect (proven fallback)
        __syncthreads();
        for (int i = tid; i < NB2; i += TPB) sh_hist[i] = 0;
        __syncthreads();
        for (int j = 0; j < NF4 / TPB; j++) {
            float4 f = src4[tid + j * TPB];
            atomicAdd(&sh_hist[fkey(f.x) >> SHIFT], 1u);
            atomicAdd(&sh_hist[fkey(f.y) >> SHIFT], 1u);
            atomicAdd(&sh_hist[fkey(f.z) >> SHIFT], 1u);
            atomicAdd(&sh_hist[fkey(f.w) >> SHIFT], 1u);
        }
        __syncthreads();
        suffix_find(sh_hist, NB2, NK, s_ws, &s_bin, &s_above);
        thrbase = s_bin << SHIFT;
        thresh  = inv_fkey(thrbase);
        rshift  = SHIFT - 8;
        if (tid == 0) s_cnt = 0;
        __syncthreads();
        for (int j = 0; j < NF4 / TPB; j++) {
            float4 f = src4[tid + j * TPB];
            push4(f, tid + j * TPB, thresh, cand, &s_cnt, CAP2);
        }
        __syncthreads();
        Mc = s_cnt;
        if (Mc > CAP2) Mc = CAP2;   // only under pathological tie storms
    }

    // ---- Phase 3: 256-bin refine to ~NK keepers ----
    if (tid < 256) rh[tid] = 0;
    if (tid == 0) s_kcnt = 0;
    __syncthreads();
    for (unsigned i = tid; i < Mc; i += TPB) {
        unsigned key = (unsigned)(cand[i] >> 16);
        unsigned off = (key - thrbase) >> rshift;
        if (off > 255u) off = 255u;
        atomicAdd(&rh[off], 1u);       // spread addresses: cheap
    }
    __syncthreads();
    suffix_find(rh, 256, NK, s_ws, &s_bin, &s_above);
    unsigned r0 = s_bin;
    for (unsigned i = tid; i < Mc; i += TPB) {
        unsigned long long e = cand[i];
        unsigned key = (unsigned)(e >> 16);
        unsigned off = (key - thrbase) >> rshift;
        if (off > 255u) off = 255u;
        if (off >= r0) {
            unsigned p = atomicAdd(&s_kcnt, 1u);
            if (p < KEEP) keep[p] = e;
        }
    }
    __syncthreads();
    unsigned kc = s_kcnt;
    unsigned long long* buf = keep;
    unsigned n = kc;
    if (kc > KEEP) { buf = cand; n = Mc; }

    // ---- Phase 4: bitonic sort desc on (key, 65535-idx) => jax tie order ----
    unsigned P2 = 128;
    while (P2 < n) P2 <<= 1;
    for (unsigned i = n + tid; i < P2; i += TPB) buf[i] = 0ULL;
    __syncthreads();

    if (P2 <= TPB) {
        // register-resident bitonic: shfl for j<32, smem for j>=32
        unsigned long long v = (tid < (int)P2) ? buf[tid] : 0ULL;
        for (unsigned k = 2; k <= P2; k <<= 1) {
            for (unsigned j = k >> 1; j > 0; j >>= 1) {
                unsigned long long o;
                if (j >= 32) {
                    if (tid < (int)P2) buf[tid] = v;
                    __syncthreads();
                    o = (tid < (int)P2) ? buf[tid ^ j] : 0ULL;
                    __syncthreads();
                } else {
                    o = __shfl_xor_sync(FULLM, v, j);
                }
                if (tid < (int)P2) {
                    bool keep_max = (((unsigned)tid & j) == 0) == (((unsigned)tid & k) == 0);
                    v = keep_max ? (v > o ? v : o) : (v < o ? v : o);
                }
            }
        }
        if (tid < (int)P2) buf[tid] = v;
        __syncthreads();
    } else {
        // pathological fallback (n > TPB): strided smem bitonic
        for (unsigned k = 2; k <= P2; k <<= 1) {
            for (unsigned j = k >> 1; j > 0; j >>= 1) {
                for (unsigned i = tid; i < P2; i += TPB) {
                    unsigned ixj = i ^ j;
                    if (ixj > i) {
                        unsigned long long a = buf[i], b = buf[ixj];
                        bool up = (i & k) == 0;
                        if (up ? (a < b) : (a > b)) { buf[i] = b; buf[ixj] = a; }
                    }
                }
                __syncthreads();
            }
        }
    }

    if (tid < NK) {
        unsigned idx = 65535u - (unsigned)(buf[tid] & 0xFFFFULL);
        g_xy[tensor][batch][tid][0] = (float)(idx & 255u);
        g_xy[tensor][batch][tid][1] = (float)(idx >> 8);
    }
    __syncthreads();

    // ---- Pair rendezvous: second finisher computes this batch's loss ----
    if (tid == 0) {
        __threadfence();
        s_sec = (atomicAdd(&g_pair[batch], 1u) == 1u);
    }
    __syncthreads();
    if (s_sec) {
        __threadfence();   // acquire: peer's g_xy / g_pre visible
        float loss = 0.f, mval = 0.f;
        if (tid < NK) {
            const float* pre = g_pre[batch][tid];
            float m  = pre[6];
            float xp = g_xy[0][batch][tid][0] * m, yp = g_xy[0][batch][tid][1] * m;
            float xt = g_xy[1][batch][tid][0] * m, yt = g_xy[1][batch][tid][1] * m;
            loss = gwd_one(xp, yp, pre[0], pre[1], pre[2],
                           xt, yt, pre[3], pre[4], pre[5]);
            mval = m;
        }
        for (int d = 16; d > 0; d >>= 1) {
            loss += __shfl_down_sync(FULLM, loss, d);
            mval += __shfl_down_sync(FULLM, mval, d);
        }
        if (lane == 0) { rl[warp] = loss; rm[warp] = mval; }
        __syncthreads();
        if (tid == 0) {
            float l = 0.f, m = 0.f;
            for (int w = 0; w < 4; w++) { l += rl[w]; m += rm[w]; }  // tid<NK<128
            g_part[batch][0] = l;
            g_part[batch][1] = m;
        }
        __syncthreads();
    }

    // ---- Overall-last block writes the final scalar ----
    if (tid == 0) {
        __threadfence();
        s_last = (atomicAdd(&g_done, 1u) == (unsigned)(NTB - 1));
    }
    __syncthreads();
    if (!s_last) return;
    __threadfence();
    if (tid < BATCH) {
        float l = g_part[tid][0], m = g_part[tid][1];
        for (int d = 16; d > 0; d >>= 1) {
            l += __shfl_down_sync(FULLM, l, d);
            m += __shfl_down_sync(FULLM, m, d);
        }
        if (lane == 0) { rl[tid >> 5] = l; rm[tid >> 5] = m; }
    }
    __syncthreads();
    if (tid == 0) {
        out[0] = (rl[0] + rl[1]) / ((rm[0] + rm[1]) + 1e-8f);
        g_done = 0;
        for (int b = 0; b < BATCH; b++) g_pair[b] = 0;   // reset for next replay
    }
}

extern "C" void kernel_launch(void* const* d_in, const int* in_sizes, int n_in,
                              void* d_out, int out_size) {
    const float* hm_p  = (const float*)d_in[0];
    const float* ab_p  = (const float*)d_in[1];
    const float* ang_p = (const float*)d_in[2];
    const float* hm_t  = (const float*)d_in[3];
    const float* ab_t  = (const float*)d_in[4];
    const float* ang_t = (const float*)d_in[5];
    const int*   ind   = (const int*)d_in[6];
    const int*   msk   = (const int*)d_in[7];
    float*       out   = (float*)d_out;

    fused_all<<<NTB, TPB>>>(hm_p, hm_t, ab_p, ang_p, ab_t, ang_t, ind, msk, out);
}

// round 17
// speedup vs baseline: 1.1816x; 1.0099x over previous
#include <cuda_runtime.h>

#define HW      65536
#define NF4     16384        // HW/4
#define BATCH   64
#define NTB     128
#define NK      100
#define SHIFT   19
#define NB2     8192
#define CAP2    2048
#define KEEP    512
#define KS1     48           // sample target on 8192 samples (~384 expected survivors)
#define TPB     1024
#define NW      (TPB / 32)
#define FULLM   0xffffffffu
#define D2R     0.017453292519943295f

__device__ float    g_xy[2][BATCH][NK][2];
__device__ float    g_pre[BATCH][NK][8];   // wp,hp,ap,wt,ht,at,m,pad
__device__ float    g_part[BATCH][2];
__device__ unsigned g_pair[BATCH];
__device__ unsigned g_done = 0;

__device__ __forceinline__ unsigned fkey(float f) {
    unsigned u = __float_as_uint(f);
    return u ^ ((unsigned)((int)u >> 31) | 0x80000000u);
}
__device__ __forceinline__ float inv_fkey(unsigned k) {
    unsigned u = (k & 0x80000000u) ? (k ^ 0x80000000u) : ~k;
    return __uint_as_float(u);
}

// Find bin b with (count in bins > b) < K <= (count in bins >= b). Block-collective.
__device__ void suffix_find(const unsigned* hist, int NB, unsigned K,
                            unsigned* s_ws, unsigned* s_bin, unsigned* s_above) {
    int tid  = threadIdx.x;
    int lane = tid & 31, warp = tid >> 5;
    int bpt  = (NB + TPB - 1) / TPB;
    int base = tid * bpt;
    unsigned p = 0;
    for (int j = 0; j < bpt; j++) {
        int b = base + j;
        if (b < NB) p += hist[b];
    }
    unsigned v = p;
    for (int d = 1; d < 32; d <<= 1) {
        unsigned o = __shfl_down_sync(FULLM, v, d);
        if (lane + d < 32) v += o;
    }
    if (lane == 0) s_ws[warp] = v;
    __syncthreads();
    unsigned add = 0;
    for (int w = warp + 1; w < NW; w++) add += s_ws[w];
    unsigned sAfter = (v - p) + add;
    if (sAfter < K && sAfter + p >= K) {
        unsigned cum = sAfter;
        for (int j = bpt - 1; j >= 0; j--) {
            int b = base + j;
            if (b >= NB) continue;
            unsigned h = hist[b];
            if (cum + h >= K) { *s_bin = (unsigned)b; *s_above = cum; break; }
            cum += h;
        }
    }
    __syncthreads();
}

__device__ __forceinline__ float gwd_one(float xp, float yp, float wp, float hp, float ap,
                                         float xt, float yt, float wt, float ht, float at) {
    wp = fminf(fmaxf(wp, 1e-7f), 1e7f);
    hp = fminf(fmaxf(hp, 1e-7f), 1e7f);
    wt = fminf(fmaxf(wt, 1e-7f), 1e7f);
    ht = fminf(fmaxf(ht, 1e-7f), 1e7f);
    float sp, cp, st, ct;
    sincosf(ap * D2R, &sp, &cp);
    sincosf(at * D2R, &st, &ct);
    float s1p = 0.5f * wp, s2p = 0.5f * hp, s1t = 0.5f * wt, s2t = 0.5f * ht;
    float dx = xp - xt, dy = yp - yt;
    float xyd = dx * dx + dy * dy;
    float q1p = s1p * s1p, q2p = s2p * s2p, q1t = s1t * s1t, q2t = s2t * s2t;
    float Ap = cp * cp * q1p + sp * sp * q2p;
    float Bp = cp * sp * (q1p - q2p);
    float Cp = sp * sp * q1p + cp * cp * q2p;
    float At = ct * ct * q1t + st * st * q2t;
    float Bt = ct * st * (q1t - q2t);
    float Ct = st * st * q1t + ct * ct * q2t;
    float whr  = q1p + q2p + q1t + q2t;
    float tr   = Ap * At + 2.f * Bp * Bt + Cp * Ct;
    float dets = s1p * s2p * s1t * s2t;
    whr -= 2.f * sqrtf(fmaxf(tr + 2.f * dets, 0.f));
    float d = fmaxf(xyd + whr, 0.f);
    d = log1pf(d);
    return 1.f - 1.f / (1.f + d);
}

__device__ __forceinline__ void push4(float4 f, int gidx4, float thresh,
                                      unsigned long long* cand, unsigned* s_cnt,
                                      unsigned cap) {
    // fast reject: 97%+ of quads have no survivor
    float mx = fmaxf(fmaxf(f.x, f.y), fmaxf(f.z, f.w));
    if (mx < thresh) return;
    float v[4] = {f.x, f.y, f.z, f.w};
#pragma unroll
    for (int c = 0; c < 4; c++) {
        if (v[c] >= thresh) {
            unsigned pos = atomicAdd(s_cnt, 1u);
            if (pos < cap) {
                unsigned idx = (unsigned)(gidx4 * 4 + c);
                cand[pos] = ((unsigned long long)fkey(v[c]) << 16) |
                            (unsigned long long)(65535u - idx);
            }
        }
    }
}

__global__ void __launch_bounds__(TPB)
fused_all(const float* __restrict__ hm_p, const float* __restrict__ hm_t,
          const float* __restrict__ ab_p, const float* __restrict__ ang_p,
          const float* __restrict__ ab_t, const float* __restrict__ ang_t,
          const int* __restrict__ ind, const int* __restrict__ msk,
          float* __restrict__ out) {
    __shared__ __align__(16) unsigned sh_hist[NB2];   // 32KB union region
    unsigned long long* cand = (unsigned long long*)sh_hist;             // [0,16K)
    unsigned long long* keep = (unsigned long long*)(sh_hist + 4096);    // [16K,20K)
    __shared__ unsigned rh[256];
    __shared__ unsigned s_ws[NW];
    __shared__ unsigned s_bin, s_above, s_cnt, s_kcnt, s_sec, s_last;
    __shared__ float rl[NW], rm[NW];

    int tid  = threadIdx.x;
    int lane = tid & 31, warp = tid >> 5;
    int tb     = blockIdx.x;              // 0..63 = hm_p, 64..127 = hm_t
    int tensor = (tb >= BATCH) ? 1 : 0;
    int batch  = tb & 63;
    const float4* src4 = (const float4*)
        (tensor ? hm_t + (size_t)batch * HW : hm_p + (size_t)batch * HW);

    // ---- Stage loss inputs (blocks 0..63, tid<NK; overlaps sample) ----
    if (tensor == 0 && tid < NK) {
        int r   = batch * NK + tid;
        float m = (float)msk[r];
        int id  = ind[r];
        size_t ab_base = (size_t)batch * (2 * HW);
        g_pre[batch][tid][0] = ab_p[ab_base + id] * 2.f * m;
        g_pre[batch][tid][1] = ab_p[ab_base + HW + id] * 2.f * m;
        g_pre[batch][tid][2] = (ang_p[(size_t)batch * HW + id] - 90.f) * m;
        g_pre[batch][tid][3] = ab_t[r * 2] * 2.f * m;
        g_pre[batch][tid][4] = ab_t[r * 2 + 1] * 2.f * m;
        g_pre[batch][tid][5] = (ang_t[r] - 90.f) * m;
        g_pre[batch][tid][6] = m;
    }

    // ---- Phase 1: 8192 coalesced samples -> 16-bit key threshold ----
    unsigned keys[8];
#pragma unroll
    for (int c = 0; c < 2; c++) {
        float4 f = src4[c * (NF4 / 2) + tid];
        keys[4 * c + 0] = fkey(f.x);
        keys[4 * c + 1] = fkey(f.y);
        keys[4 * c + 2] = fkey(f.z);
        keys[4 * c + 3] = fkey(f.w);
    }
    if (tid < 256) rh[tid] = 0;
    __syncthreads();
#pragma unroll
    for (int i = 0; i < 8; i++) atomicAdd(&rh[keys[i] >> 24], 1u);
    __syncthreads();
    suffix_find(rh, 256, KS1, s_ws, &s_bin, &s_above);
    unsigned c0 = s_bin, a0 = s_above;
    __syncthreads();
    if (tid < 256) rh[tid] = 0;
    __syncthreads();
#pragma unroll
    for (int i = 0; i < 8; i++)
        if ((keys[i] >> 24) == c0) atomicAdd(&rh[(keys[i] >> 16) & 255u], 1u);
    __syncthreads();
    suffix_find(rh, 256, KS1 - a0, s_ws, &s_bin, &s_above);
    unsigned thrkey = (c0 << 24) | (s_bin << 16);
    float thresh = inv_fkey(thrkey);

    // ---- Phase 2: one full streaming pass, 8-deep batched loads ----
    if (tid == 0) s_cnt = 0;
    __syncthreads();
#pragma unroll
    for (int b = 0; b < 2; b++) {
        float4 fa[8];
#pragma unroll
        for (int u = 0; u < 8; u++)
            fa[u] = __ldcs(&src4[tid + (8 * b + u) * TPB]);
#pragma unroll
        for (int u = 0; u < 8; u++)
            push4(fa[u], tid + (8 * b + u) * TPB, thresh, cand, &s_cnt, CAP2);
    }
    __syncthreads();
    unsigned Mc = s_cnt;
    unsigned rshift = 9;
    unsigned thrbase = thrkey;
    bool need_exact = (Mc < NK) || (Mc > CAP2);

    if (need_exact) {
        // exact 13-bit histogram + recollect (proven fallback)
        __syncthreads();
        for (int i = tid; i < NB2; i += TPB) sh_hist[i] = 0;
        __syncthreads();
        for (int j = 0; j < NF4 / TPB; j++) {
            float4 f = src4[tid + j * TPB];
            atomicAdd(&sh_hist[fkey(f.x) >> SHIFT], 1u);
            atomicAdd(&sh_hist[fkey(f.y) >> SHIFT], 1u);
            atomicAdd(&sh_hist[fkey(f.z) >> SHIFT], 1u);
            atomicAdd(&sh_hist[fkey(f.w) >> SHIFT], 1u);
        }
        __syncthreads();
        suffix_find(sh_hist, NB2, NK, s_ws, &s_bin, &s_above);
        thrbase = s_bin << SHIFT;
        thresh  = inv_fkey(thrbase);
        rshift  = SHIFT - 8;
        if (tid == 0) s_cnt = 0;
        __syncthreads();
        for (int j = 0; j < NF4 / TPB; j++) {
            float4 f = src4[tid + j * TPB];
            push4(f, tid + j * TPB, thresh, cand, &s_cnt, CAP2);
        }
        __syncthreads();
        Mc = s_cnt;
        if (Mc > CAP2) Mc = CAP2;   // only under pathological tie storms
    }

    // ---- Phase 3: 256-bin refine to ~NK keepers ----
    if (tid < 256) rh[tid] = 0;
    if (tid == 0) s_kcnt = 0;
    __syncthreads();
    for (unsigned i = tid; i < Mc; i += TPB) {
        unsigned key = (unsigned)(cand[i] >> 16);
        unsigned off = (key - thrbase) >> rshift;
        if (off > 255u) off = 255u;
        atomicAdd(&rh[off], 1u);       // spread addresses: cheap
    }
    __syncthreads();
    suffix_find(rh, 256, NK, s_ws, &s_bin, &s_above);
    unsigned r0 = s_bin;
    for (unsigned i = tid; i < Mc; i += TPB) {
        unsigned long long e = cand[i];
        unsigned key = (unsigned)(e >> 16);
        unsigned off = (key - thrbase) >> rshift;
        if (off > 255u) off = 255u;
        if (off >= r0) {
            unsigned p = atomicAdd(&s_kcnt, 1u);
            if (p < KEEP) keep[p] = e;
        }
    }
    __syncthreads();
    unsigned kc = s_kcnt;
    unsigned long long* buf = keep;
    unsigned n = kc;
    if (kc > KEEP) { buf = cand; n = Mc; }

    // ---- Phase 4: bitonic sort desc on (key, 65535-idx) => jax tie order ----
    unsigned P2 = 128;
    while (P2 < n) P2 <<= 1;
    for (unsigned i = n + tid; i < P2; i += TPB) buf[i] = 0ULL;
    __syncthreads();

    if (P2 <= TPB) {
        // register-resident bitonic: shfl for j<32, smem for j>=32
        unsigned long long v = (tid < (int)P2) ? buf[tid] : 0ULL;
        for (unsigned k = 2; k <= P2; k <<= 1) {
            for (unsigned j = k >> 1; j > 0; j >>= 1) {
                unsigned long long o;
                if (j >= 32) {
                    if (tid < (int)P2) buf[tid] = v;
                    __syncthreads();
                    o = (tid < (int)P2) ? buf[tid ^ j] : 0ULL;
                    __syncthreads();
                } else {
                    o = __shfl_xor_sync(FULLM, v, j);
                }
                if (tid < (int)P2) {
                    bool keep_max = (((unsigned)tid & j) == 0) == (((unsigned)tid & k) == 0);
                    v = keep_max ? (v > o ? v : o) : (v < o ? v : o);
                }
            }
        }
        if (tid < (int)P2) buf[tid] = v;
        __syncthreads();
    } else {
        // pathological fallback (n > TPB): strided smem bitonic
        for (unsigned k = 2; k <= P2; k <<= 1) {
            for (unsigned j = k >> 1; j > 0; j >>= 1) {
                for (unsigned i = tid; i < P2; i += TPB) {
                    unsigned ixj = i ^ j;
                    if (ixj > i) {
                        unsigned long long a = buf[i], b = buf[ixj];
                        bool up = (i & k) == 0;
                        if (up ? (a < b) : (a > b)) { buf[i] = b; buf[ixj] = a; }
                    }
                }
                __syncthreads();
            }
        }
    }

    if (tid < NK) {
        unsigned idx = 65535u - (unsigned)(buf[tid] & 0xFFFFULL);
        g_xy[tensor][batch][tid][0] = (float)(idx & 255u);
        g_xy[tensor][batch][tid][1] = (float)(idx >> 8);
    }
    __syncthreads();

    // ---- Pair rendezvous: second finisher computes this batch's loss ----
    if (tid == 0) {
        __threadfence();
        s_sec = (atomicAdd(&g_pair[batch], 1u) == 1u);
    }
    __syncthreads();
    if (s_sec) {
        __threadfence();   // acquire: peer's g_xy / g_pre visible
        float loss = 0.f, mval = 0.f;
        if (tid < NK) {
            const float* pre = g_pre[batch][tid];
            float m  = pre[6];
            float xp = g_xy[0][batch][tid][0] * m, yp = g_xy[0][batch][tid][1] * m;
            float xt = g_xy[1][batch][tid][0] * m, yt = g_xy[1][batch][tid][1] * m;
            loss = gwd_one(xp, yp, pre[0], pre[1], pre[2],
                           xt, yt, pre[3], pre[4], pre[5]);
            mval = m;
        }
        for (int d = 16; d > 0; d >>= 1) {
            loss += __shfl_down_sync(FULLM, loss, d);
            mval += __shfl_down_sync(FULLM, mval, d);
        }
        if (lane == 0) { rl[warp] = loss; rm[warp] = mval; }
        __syncthreads();
        if (tid == 0) {
            float l = 0.f, m = 0.f;
            for (int w = 0; w < 4; w++) { l += rl[w]; m += rm[w]; }  // tid<NK<128
            g_part[batch][0] = l;
            g_part[batch][1] = m;
        }
        __syncthreads();
    }

    // ---- Overall-last block writes the final scalar ----
    if (tid == 0) {
        __threadfence();
        s_last = (atomicAdd(&g_done, 1u) == (unsigned)(NTB - 1));
    }
    __syncthreads();
    if (!s_last) return;
    __threadfence();
    if (tid < BATCH) {
        float l = g_part[tid][0], m = g_part[tid][1];
        for (int d = 16; d > 0; d >>= 1) {
            l += __shfl_down_sync(FULLM, l, d);
            m += __shfl_down_sync(FULLM, m, d);
        }
        if (lane == 0) { rl[tid >> 5] = l; rm[tid >> 5] = m; }
    }
    __syncthreads();
    if (tid == 0) {
        out[0] = (rl[0] + rl[1]) / ((rm[0] + rm[1]) + 1e-8f);
        g_done = 0;
        for (int b = 0; b < BATCH; b++) g_pair[b] = 0;   // reset for next replay
    }
}

extern "C" void kernel_launch(void* const* d_in, const int* in_sizes, int n_in,
                              void* d_out, int out_size) {
    const float* hm_p  = (const float*)d_in[0];
    const float* ab_p  = (const float*)d_in[1];
    const float* ang_p = (const float*)d_in[2];
    const float* hm_t  = (const float*)d_in[3];
    const float* ab_t  = (const float*)d_in[4];
    const float* ang_t = (const float*)d_in[5];
    const int*   ind   = (const int*)d_in[6];
    const int*   msk   = (const int*)d_in[7];
    float*       out   = (float*)d_out;

    fused_all<<<NTB, TPB>>>(hm_p, hm_t, ab_p, ang_p, ab_t, ang_t, ind, msk, out);
}